// round 11
// baseline (speedup 1.0000x reference)
#include <cuda_runtime.h>
#include <cuda_bf16.h>
#include <cstdint>

// ============================================================================
// Supervised contrastive loss, B=8192, D=256, NUM_CLASSES=100, T=0.07
//
// R11 = best-of-R9/R10:
//  - separate k_prep (1024 thr) + k_cvt (prep merge reverted: it regressed)
//  - k_gemm: __launch_bounds__(256, 1)  <-- KEY: (256,2) capped regs at 128
//    while acc[] alone needs 128 live regs -> ptxas was SPILLING accumulators
//    to local memory in the mainloop. occ 1 gives 255 regs, zero spills.
//  - 4-stage all-K prefetch + register-cached epilogue kept from R10
//  - warp-per-row rowloss with fused finalize (R9)
// ============================================================================

#define B_N   8192
#define D_K   256
#define NCLS  100
#define INV_T 14.285714285714285714f
#define DSCL  (1.f / 65536.f)
#define EC    (DSCL * INV_T)
#define MAT_CAP (1 << 21)

// ---- scratch ----
__device__ int8_t g_zq[B_N * D_K];
__device__ int    g_lab[B_N];
__device__ int    g_rank[B_N];
__device__ int    g_cls_cnt[NCLS];
__device__ int    g_mat_off[NCLS];
__device__ float  g_mat[MAT_CAP];
__device__ float  g_sumneg[B_N];
__device__ float  g_loss_sum;
__device__ int    g_valid;
__device__ int    g_done;

// ============================================================================
// K0: prep (1024 threads, single block)
// ============================================================================
__global__ void k_prep(const void* lab_raw) {
    __shared__ int s_nonzero;
    __shared__ int s_cnt[NCLS];
    __shared__ int s_fill[NCLS];

    const int t = threadIdx.x;
    if (t == 0) s_nonzero = 0;
    for (int c = t; c < NCLS; c += blockDim.x) { s_cnt[c] = 0; s_fill[c] = 0; }
    __syncthreads();

    const int* p32 = (const int*)lab_raw;
    // int64 LE labels in [0,100): every odd 32-bit word is 0.
    int local = 0;
    for (int i = t; i < B_N / 2; i += blockDim.x)
        if (p32[2 * i + 1] != 0) local = 1;
    if (local) atomicOr(&s_nonzero, 1);
    __syncthreads();
    const bool is64 = (s_nonzero == 0);

    for (int i = t; i < B_N; i += blockDim.x) {
        int l = is64 ? p32[2 * i] : p32[i];
        g_lab[i]    = l;
        g_sumneg[i] = 0.f;
        atomicAdd(&s_cnt[l], 1);
    }
    if (t == 0) { g_loss_sum = 0.f; g_valid = 0; g_done = 0; }
    __syncthreads();

    if (t == 0) {
        int acc = 0;
        for (int c = 0; c < NCLS; c++) {
            g_cls_cnt[c] = s_cnt[c];
            g_mat_off[c] = acc;
            acc += s_cnt[c] * s_cnt[c];
        }
    }
    __syncthreads();

    for (int i = t; i < B_N; i += blockDim.x)
        g_rank[i] = atomicAdd(&s_fill[g_lab[i]], 1);
}

// ============================================================================
// K1: fp32 -> int8
// ============================================================================
__global__ __launch_bounds__(256) void k_cvt(const float* __restrict__ z) {
    int i = blockIdx.x * blockDim.x + threadIdx.x;
    float4 v = ((const float4*)z)[i];
    int a = max(-127, min(127, __float2int_rn(v.x * 256.f)));
    int b = max(-127, min(127, __float2int_rn(v.y * 256.f)));
    int c = max(-127, min(127, __float2int_rn(v.z * 256.f)));
    int d = max(-127, min(127, __float2int_rn(v.w * 256.f)));
    uint32_t p = (uint32_t)(a & 255) | ((uint32_t)(b & 255) << 8) |
                 ((uint32_t)(c & 255) << 16) | ((uint32_t)(d & 255) << 24);
    ((uint32_t*)g_zq)[i] = p;
}

// ============================================================================
// K2: symmetric fused INT8 GEMM, 4-stage all-K prefetch, occ 1 (no spills)
// ============================================================================
#define BM   128
#define BN   128
#define BK   64
#define NBLK (B_N / BM)    // 64
#define LDTB 80
#define STAGE (BM * LDTB)
#define SM_A     0
#define SM_B     (4 * STAGE)
#define SM_MISC  (8 * STAGE)
#define SM_RLAB  (SM_MISC)
#define SM_CLAB  (SM_MISC + 512)
#define SM_RRANK (SM_MISC + 1024)
#define SM_CRANK (SM_MISC + 1536)
#define SM_RBASE (SM_MISC + 2048)
#define SM_RN    (SM_MISC + 2560)
#define SM_ROWS  (SM_MISC + 3072)
#define SM_COLS  (SM_MISC + 3584)
#define SMEM_GEMM (SM_MISC + 4096)     // 86016 B

__device__ __forceinline__ void cp16(uint32_t dst, const void* src) {
    asm volatile("cp.async.cg.shared.global [%0], [%1], 16;\n" :: "r"(dst), "l"(src));
}

__device__ __forceinline__ void imma16832(int* c, const uint32_t* a, const uint32_t* b) {
    asm volatile(
        "mma.sync.aligned.m16n8k32.row.col.s32.s8.s8.s32 "
        "{%0,%1,%2,%3}, {%4,%5,%6,%7}, {%8,%9}, {%0,%1,%2,%3};"
        : "+r"(c[0]), "+r"(c[1]), "+r"(c[2]), "+r"(c[3])
        : "r"(a[0]), "r"(a[1]), "r"(a[2]), "r"(a[3]), "r"(b[0]), "r"(b[1]));
}

__global__ __launch_bounds__(256, 1) void k_gemm() {
    extern __shared__ __align__(16) char smem[];
    uint32_t sb;
    asm("{ .reg .u64 tmp; cvta.to.shared.u64 tmp, %1; cvt.u32.u64 %0, tmp; }"
        : "=r"(sb) : "l"(smem));

    int*   s_rlab  = (int*)(smem + SM_RLAB);
    int*   s_clab  = (int*)(smem + SM_CLAB);
    int*   s_rrank = (int*)(smem + SM_RRANK);
    int*   s_crank = (int*)(smem + SM_CRANK);
    int*   s_rbase = (int*)(smem + SM_RBASE);
    int*   s_rn    = (int*)(smem + SM_RN);
    float* s_rows  = (float*)(smem + SM_ROWS);
    float* s_cols  = (float*)(smem + SM_COLS);

    const int t    = threadIdx.x;
    const int warp = t >> 5;
    const int lane = t & 31;
    const int wm   = warp >> 2;
    const int wn   = warp & 3;

    // triangular decode: bid -> (bi, bj), bj >= bi
    int bi = 0, rem = blockIdx.x;
    #pragma unroll 1
    while (rem >= NBLK - bi) { rem -= NBLK - bi; bi++; }
    const int  bj   = bi + rem;
    const bool diag = (bi == bj);
    const int iBase = bi * BM;
    const int jBase = bj * BN;

    const int8_t* gA = g_zq + (size_t)iBase * D_K;
    const int8_t* gB = g_zq + (size_t)jBase * D_K;

    // issue ALL K chunk loads up front (4 commit groups)
    {
        const int row = t >> 2, ch = t & 3;
        const int row2 = (t + 256) >> 2, ch2 = (t + 256) & 3;
        #pragma unroll
        for (int kt = 0; kt < 4; kt++) {
            int k0 = kt * BK;
            uint32_t so  = (uint32_t)(row  * LDTB + ch  * 16) + kt * STAGE;
            uint32_t so2 = (uint32_t)(row2 * LDTB + ch2 * 16) + kt * STAGE;
            cp16(sb + SM_A + so,  gA + (size_t)row  * D_K + k0 + ch  * 16);
            cp16(sb + SM_B + so,  gB + (size_t)row  * D_K + k0 + ch  * 16);
            cp16(sb + SM_A + so2, gA + (size_t)row2 * D_K + k0 + ch2 * 16);
            cp16(sb + SM_B + so2, gB + (size_t)row2 * D_K + k0 + ch2 * 16);
            asm volatile("cp.async.commit_group;\n" ::);
        }
    }

    if (t < BM) {
        int lr = g_lab[iBase + t];
        s_rlab[t]  = lr;
        s_clab[t]  = g_lab[jBase + t];
        s_rrank[t] = g_rank[iBase + t];
        s_crank[t] = g_rank[jBase + t];
        s_rbase[t] = g_mat_off[lr];
        s_rn[t]    = g_cls_cnt[lr];
        s_rows[t]  = 0.f;
        s_cols[t]  = 0.f;
    }

    int acc[4][4][4];
    #pragma unroll
    for (int a = 0; a < 4; a++)
        #pragma unroll
        for (int b = 0; b < 4; b++)
            #pragma unroll
            for (int r = 0; r < 4; r++) acc[a][b][r] = 0;

    #pragma unroll
    for (int kt = 0; kt < 4; kt++) {
        if (kt == 0)      asm volatile("cp.async.wait_group 3;\n" ::);
        else if (kt == 1) asm volatile("cp.async.wait_group 2;\n" ::);
        else if (kt == 2) asm volatile("cp.async.wait_group 1;\n" ::);
        else              asm volatile("cp.async.wait_group 0;\n" ::);
        __syncthreads();

        const uint32_t aS = sb + SM_A + kt * STAGE;
        const uint32_t bS = sb + SM_B + kt * STAGE;

        #pragma unroll
        for (int ks = 0; ks < 2; ks++) {
            const int kb = ks * 32;
            uint32_t af[4][4], bf[4][2];
            #pragma unroll
            for (int mi = 0; mi < 4; mi++) {
                int r = wm * 64 + mi * 16 + (lane & 15);
                int c = kb + ((lane >> 4) << 4);
                uint32_t addr = aS + (uint32_t)(r * LDTB + c);
                asm volatile(
                    "ldmatrix.sync.aligned.m8n8.x4.shared.b16 {%0,%1,%2,%3}, [%4];"
                    : "=r"(af[mi][0]), "=r"(af[mi][1]), "=r"(af[mi][2]), "=r"(af[mi][3])
                    : "r"(addr));
            }
            #pragma unroll
            for (int p = 0; p < 2; p++) {
                int m  = lane >> 3;
                int nr = wn * 32 + (p * 2 + (m >> 1)) * 8 + (lane & 7);
                int c  = kb + ((m & 1) << 4);
                uint32_t addr = bS + (uint32_t)(nr * LDTB + c);
                asm volatile(
                    "ldmatrix.sync.aligned.m8n8.x4.shared.b16 {%0,%1,%2,%3}, [%4];"
                    : "=r"(bf[2 * p][0]), "=r"(bf[2 * p][1]),
                      "=r"(bf[2 * p + 1][0]), "=r"(bf[2 * p + 1][1])
                    : "r"(addr));
            }
            #pragma unroll
            for (int mi = 0; mi < 4; mi++)
                #pragma unroll
                for (int ni = 0; ni < 4; ni++)
                    imma16832(acc[mi][ni], af[mi], bf[ni]);
        }
    }
    __syncthreads();

    // ---- epilogue ----
    const int qrow = lane >> 2;
    const int qcol = (lane & 3) * 2;

    int clab[8], crank[8];
    #pragma unroll
    for (int x = 0; x < 8; x++) {
        int c = wn * 32 + (x >> 1) * 8 + qcol + (x & 1);
        clab[x]  = s_clab[c];
        crank[x] = s_crank[c];
    }

    auto emit = [&](int r, int rjx, float d) {
        int base = s_rbase[r], n = s_rn[r];
        g_mat[base + s_rrank[r] * n + crank[rjx]] = d;
        if (!diag) g_mat[base + crank[rjx] * n + s_rrank[r]] = d;
    };

    float csum[8];
    #pragma unroll
    for (int x = 0; x < 8; x++) csum[x] = 0.f;

    #pragma unroll
    for (int mi = 0; mi < 4; mi++) {
        int r0  = wm * 64 + mi * 16 + qrow;
        int lr0 = s_rlab[r0];
        int lr1 = s_rlab[r0 + 8];
        float s0 = 0.f, s1 = 0.f;
        #pragma unroll
        for (int ni = 0; ni < 4; ni++) {
            int c0  = wn * 32 + ni * 8 + qcol;
            int lc0 = clab[ni * 2];
            int lc1 = clab[ni * 2 + 1];
            float f00 = (float)acc[mi][ni][0];
            float f01 = (float)acc[mi][ni][1];
            float f10 = (float)acc[mi][ni][2];
            float f11 = (float)acc[mi][ni][3];
            float e00 = (lr0 != lc0) ? __expf(f00 * EC) : 0.f;
            float e01 = (lr0 != lc1) ? __expf(f01 * EC) : 0.f;
            float e10 = (lr1 != lc0) ? __expf(f10 * EC) : 0.f;
            float e11 = (lr1 != lc1) ? __expf(f11 * EC) : 0.f;
            s0 += e00 + e01;
            s1 += e10 + e11;
            csum[ni * 2]     += e00 + e10;
            csum[ni * 2 + 1] += e01 + e11;
            if (lr0 == lc0 && (!diag || r0 != c0))
                emit(r0, ni * 2, f00 * DSCL);
            if (lr0 == lc1 && (!diag || r0 != c0 + 1))
                emit(r0, ni * 2 + 1, f01 * DSCL);
            if (lr1 == lc0 && (!diag || r0 + 8 != c0))
                emit(r0 + 8, ni * 2, f10 * DSCL);
            if (lr1 == lc1 && (!diag || r0 + 8 != c0 + 1))
                emit(r0 + 8, ni * 2 + 1, f11 * DSCL);
        }
        s0 += __shfl_xor_sync(0xffffffffu, s0, 1);
        s0 += __shfl_xor_sync(0xffffffffu, s0, 2);
        s1 += __shfl_xor_sync(0xffffffffu, s1, 1);
        s1 += __shfl_xor_sync(0xffffffffu, s1, 2);
        if ((lane & 3) == 0) {
            atomicAdd(&s_rows[r0],     s0);
            atomicAdd(&s_rows[r0 + 8], s1);
        }
    }

    if (!diag) {
        #pragma unroll
        for (int x = 0; x < 8; x++) {
            float cs = csum[x];
            #pragma unroll
            for (int o = 4; o <= 16; o <<= 1)
                cs += __shfl_xor_sync(0xffffffffu, cs, o);
            if (lane < 4)
                atomicAdd(&s_cols[wn * 32 + (x >> 1) * 8 + qcol + (x & 1)], cs);
        }
    }
    __syncthreads();
    if (t < BM) {
        atomicAdd(&g_sumneg[iBase + t], s_rows[t]);
        if (!diag) atomicAdd(&g_sumneg[jBase + t], s_cols[t]);
    }
}

// ============================================================================
// K3: per-row positive loss (warp per row) + fused finalize
// ============================================================================
__global__ __launch_bounds__(256) void k_rowloss(float* out) {
    __shared__ float s_p[8];
    __shared__ int   s_v[8];

    const int warp = threadIdx.x >> 5;
    const int lane = threadIdx.x & 31;
    const int i    = blockIdx.x * 8 + warp;

    const int l = g_lab[i];
    const int n = g_cls_cnt[l];
    float s = 0.f;
    if (n >= 2) {
        const int ri = g_rank[i];
        const float* row = g_mat + g_mat_off[l] + (size_t)ri * n;
        const float sn = g_sumneg[i];
        for (int rj = lane; rj < n; rj += 32)
            if (rj != ri)
                s += log1pf(sn * __expf(-row[rj] * INV_T));
        #pragma unroll
        for (int o = 16; o; o >>= 1)
            s += __shfl_xor_sync(0xffffffffu, s, o);
    }
    if (lane == 0) {
        s_p[warp] = (n >= 2) ? s / (float)(n - 1) : 0.f;
        s_v[warp] = (n >= 2) ? 1 : 0;
    }
    __syncthreads();
    if (threadIdx.x == 0) {
        float tp = 0.f; int tv = 0;
        #pragma unroll
        for (int w = 0; w < 8; w++) { tp += s_p[w]; tv += s_v[w]; }
        atomicAdd(&g_loss_sum, tp);
        atomicAdd(&g_valid, tv);
        __threadfence();
        int d = atomicAdd(&g_done, 1);
        if (d == gridDim.x - 1) {
            int v = g_valid;
            out[0] = (v > 0) ? g_loss_sum / (float)v : 0.f;
        }
    }
}

// ============================================================================
// launch
// ============================================================================
extern "C" void kernel_launch(void* const* d_in, const int* in_sizes, int n_in,
                              void* d_out, int out_size) {
    const float* z   = (const float*)d_in[0];
    const void*  lab = d_in[1];

    cudaFuncSetAttribute(k_gemm, cudaFuncAttributeMaxDynamicSharedMemorySize,
                         SMEM_GEMM);

    k_prep<<<1, 1024>>>(lab);
    k_cvt<<<(B_N * D_K / 4) / 256, 256>>>(z);
    k_gemm<<<NBLK * (NBLK + 1) / 2, 256, SMEM_GEMM>>>();
    k_rowloss<<<B_N / 8, 256>>>((float*)d_out);
}

// round 12
// speedup vs baseline: 1.1699x; 1.1699x over previous
#include <cuda_runtime.h>
#include <cuda_bf16.h>
#include <cstdint>

// ============================================================================
// Supervised contrastive loss, B=8192, D=256, NUM_CLASSES=100, T=0.07
//
// R12: k_gemm re-tiled to ONE 512-thread CTA per 128x128 tile:
//   - 16 warps/SM (restores R9's latency hiding; R11's occ-1 with 8 warps
//     regressed 45us)
//   - acc shrinks to [2][4][4] = 32 regs/thread -> ~90 regs total, far under
//     the 128-reg cap at (512,1): zero accumulator spills by construction
//   - 4-stage all-K cp.async prefetch, one __syncthreads per chunk
// k_prep / k_cvt / k_rowloss identical to the R9 winner (94.5us).
// ============================================================================

#define B_N   8192
#define D_K   256
#define NCLS  100
#define INV_T 14.285714285714285714f
#define DSCL  (1.f / 65536.f)
#define EC    (DSCL * INV_T)
#define MAT_CAP (1 << 21)

// ---- scratch ----
__device__ int8_t g_zq[B_N * D_K];
__device__ int    g_lab[B_N];
__device__ int    g_rank[B_N];
__device__ int    g_cls_cnt[NCLS];
__device__ int    g_mat_off[NCLS];
__device__ float  g_mat[MAT_CAP];
__device__ float  g_sumneg[B_N];
__device__ float  g_loss_sum;
__device__ int    g_valid;
__device__ int    g_done;

// ============================================================================
// K0: prep (1024 threads, single block)
// ============================================================================
__global__ void k_prep(const void* lab_raw) {
    __shared__ int s_nonzero;
    __shared__ int s_cnt[NCLS];
    __shared__ int s_fill[NCLS];

    const int t = threadIdx.x;
    if (t == 0) s_nonzero = 0;
    for (int c = t; c < NCLS; c += blockDim.x) { s_cnt[c] = 0; s_fill[c] = 0; }
    __syncthreads();

    const int* p32 = (const int*)lab_raw;
    // int64 LE labels in [0,100): every odd 32-bit word is 0.
    int local = 0;
    for (int i = t; i < B_N / 2; i += blockDim.x)
        if (p32[2 * i + 1] != 0) local = 1;
    if (local) atomicOr(&s_nonzero, 1);
    __syncthreads();
    const bool is64 = (s_nonzero == 0);

    for (int i = t; i < B_N; i += blockDim.x) {
        int l = is64 ? p32[2 * i] : p32[i];
        g_lab[i]    = l;
        g_sumneg[i] = 0.f;
        atomicAdd(&s_cnt[l], 1);
    }
    if (t == 0) { g_loss_sum = 0.f; g_valid = 0; g_done = 0; }
    __syncthreads();

    if (t == 0) {
        int acc = 0;
        for (int c = 0; c < NCLS; c++) {
            g_cls_cnt[c] = s_cnt[c];
            g_mat_off[c] = acc;
            acc += s_cnt[c] * s_cnt[c];
        }
    }
    __syncthreads();

    for (int i = t; i < B_N; i += blockDim.x)
        g_rank[i] = atomicAdd(&s_fill[g_lab[i]], 1);
}

// ============================================================================
// K1: fp32 -> int8
// ============================================================================
__global__ __launch_bounds__(256) void k_cvt(const float* __restrict__ z) {
    int i = blockIdx.x * blockDim.x + threadIdx.x;
    float4 v = ((const float4*)z)[i];
    int a = max(-127, min(127, __float2int_rn(v.x * 256.f)));
    int b = max(-127, min(127, __float2int_rn(v.y * 256.f)));
    int c = max(-127, min(127, __float2int_rn(v.z * 256.f)));
    int d = max(-127, min(127, __float2int_rn(v.w * 256.f)));
    uint32_t p = (uint32_t)(a & 255) | ((uint32_t)(b & 255) << 8) |
                 ((uint32_t)(c & 255) << 16) | ((uint32_t)(d & 255) << 24);
    ((uint32_t*)g_zq)[i] = p;
}

// ============================================================================
// K2: symmetric fused INT8 GEMM — 512 threads/tile, 32 acc regs/thread
// ============================================================================
#define BM   128
#define BN   128
#define BK   64
#define NBLK (B_N / BM)    // 64
#define LDTB 80
#define STAGE (BM * LDTB)
#define SM_A     0
#define SM_B     (4 * STAGE)
#define SM_MISC  (8 * STAGE)
#define SM_RLAB  (SM_MISC)
#define SM_CLAB  (SM_MISC + 512)
#define SM_RRANK (SM_MISC + 1024)
#define SM_CRANK (SM_MISC + 1536)
#define SM_RBASE (SM_MISC + 2048)
#define SM_RN    (SM_MISC + 2560)
#define SM_ROWS  (SM_MISC + 3072)
#define SM_COLS  (SM_MISC + 3584)
#define SMEM_GEMM (SM_MISC + 4096)     // 86016 B

__device__ __forceinline__ void cp16(uint32_t dst, const void* src) {
    asm volatile("cp.async.cg.shared.global [%0], [%1], 16;\n" :: "r"(dst), "l"(src));
}

__device__ __forceinline__ void imma16832(int* c, const uint32_t* a, const uint32_t* b) {
    asm volatile(
        "mma.sync.aligned.m16n8k32.row.col.s32.s8.s8.s32 "
        "{%0,%1,%2,%3}, {%4,%5,%6,%7}, {%8,%9}, {%0,%1,%2,%3};"
        : "+r"(c[0]), "+r"(c[1]), "+r"(c[2]), "+r"(c[3])
        : "r"(a[0]), "r"(a[1]), "r"(a[2]), "r"(a[3]), "r"(b[0]), "r"(b[1]));
}

__global__ __launch_bounds__(512, 1) void k_gemm() {
    extern __shared__ __align__(16) char smem[];
    uint32_t sb;
    asm("{ .reg .u64 tmp; cvta.to.shared.u64 tmp, %1; cvt.u32.u64 %0, tmp; }"
        : "=r"(sb) : "l"(smem));

    int*   s_rlab  = (int*)(smem + SM_RLAB);
    int*   s_clab  = (int*)(smem + SM_CLAB);
    int*   s_rrank = (int*)(smem + SM_RRANK);
    int*   s_crank = (int*)(smem + SM_CRANK);
    int*   s_rbase = (int*)(smem + SM_RBASE);
    int*   s_rn    = (int*)(smem + SM_RN);
    float* s_rows  = (float*)(smem + SM_ROWS);
    float* s_cols  = (float*)(smem + SM_COLS);

    const int t    = threadIdx.x;
    const int warp = t >> 5;      // 0..15
    const int lane = t & 31;
    const int wm   = warp >> 2;   // 0..3  (32-row band)
    const int wn   = warp & 3;    // 0..3  (32-col band)

    // triangular decode: bid -> (bi, bj), bj >= bi
    int bi = 0, rem = blockIdx.x;
    #pragma unroll 1
    while (rem >= NBLK - bi) { rem -= NBLK - bi; bi++; }
    const int  bj   = bi + rem;
    const bool diag = (bi == bj);
    const int iBase = bi * BM;
    const int jBase = bj * BN;

    const int8_t* gA = g_zq + (size_t)iBase * D_K;
    const int8_t* gB = g_zq + (size_t)jBase * D_K;

    // issue ALL K chunk loads up front (4 commit groups); 1 chunk/thread/matrix
    {
        const int row = t >> 2, ch = t & 3;     // 512 threads = 512 chunks
        #pragma unroll
        for (int kt = 0; kt < 4; kt++) {
            int k0 = kt * BK;
            uint32_t so = (uint32_t)(row * LDTB + ch * 16) + kt * STAGE;
            cp16(sb + SM_A + so, gA + (size_t)row * D_K + k0 + ch * 16);
            cp16(sb + SM_B + so, gB + (size_t)row * D_K + k0 + ch * 16);
            asm volatile("cp.async.commit_group;\n" ::);
        }
    }

    if (t < BM) {
        int lr = g_lab[iBase + t];
        s_rlab[t]  = lr;
        s_clab[t]  = g_lab[jBase + t];
        s_rrank[t] = g_rank[iBase + t];
        s_crank[t] = g_rank[jBase + t];
        s_rbase[t] = g_mat_off[lr];
        s_rn[t]    = g_cls_cnt[lr];
        s_rows[t]  = 0.f;
        s_cols[t]  = 0.f;
    }

    int acc[2][4][4];
    #pragma unroll
    for (int a = 0; a < 2; a++)
        #pragma unroll
        for (int b = 0; b < 4; b++)
            #pragma unroll
            for (int r = 0; r < 4; r++) acc[a][b][r] = 0;

    #pragma unroll
    for (int kt = 0; kt < 4; kt++) {
        if (kt == 0)      asm volatile("cp.async.wait_group 3;\n" ::);
        else if (kt == 1) asm volatile("cp.async.wait_group 2;\n" ::);
        else if (kt == 2) asm volatile("cp.async.wait_group 1;\n" ::);
        else              asm volatile("cp.async.wait_group 0;\n" ::);
        __syncthreads();

        const uint32_t aS = sb + SM_A + kt * STAGE;
        const uint32_t bS = sb + SM_B + kt * STAGE;

        #pragma unroll
        for (int ks = 0; ks < 2; ks++) {
            const int kb = ks * 32;
            uint32_t af[2][4], bf[4][2];
            #pragma unroll
            for (int mi = 0; mi < 2; mi++) {
                int r = wm * 32 + mi * 16 + (lane & 15);
                int c = kb + ((lane >> 4) << 4);
                uint32_t addr = aS + (uint32_t)(r * LDTB + c);
                asm volatile(
                    "ldmatrix.sync.aligned.m8n8.x4.shared.b16 {%0,%1,%2,%3}, [%4];"
                    : "=r"(af[mi][0]), "=r"(af[mi][1]), "=r"(af[mi][2]), "=r"(af[mi][3])
                    : "r"(addr));
            }
            #pragma unroll
            for (int p = 0; p < 2; p++) {
                int m  = lane >> 3;
                int nr = wn * 32 + (p * 2 + (m >> 1)) * 8 + (lane & 7);
                int c  = kb + ((m & 1) << 4);
                uint32_t addr = bS + (uint32_t)(nr * LDTB + c);
                asm volatile(
                    "ldmatrix.sync.aligned.m8n8.x4.shared.b16 {%0,%1,%2,%3}, [%4];"
                    : "=r"(bf[2 * p][0]), "=r"(bf[2 * p][1]),
                      "=r"(bf[2 * p + 1][0]), "=r"(bf[2 * p + 1][1])
                    : "r"(addr));
            }
            #pragma unroll
            for (int mi = 0; mi < 2; mi++)
                #pragma unroll
                for (int ni = 0; ni < 4; ni++)
                    imma16832(acc[mi][ni], af[mi], bf[ni]);
        }
    }
    __syncthreads();

    // ---- epilogue ----
    const int qrow = lane >> 2;
    const int qcol = (lane & 3) * 2;

    int clab[8], crank[8];
    #pragma unroll
    for (int x = 0; x < 8; x++) {
        int c = wn * 32 + (x >> 1) * 8 + qcol + (x & 1);
        clab[x]  = s_clab[c];
        crank[x] = s_crank[c];
    }

    auto emit = [&](int r, int rjx, float d) {
        int base = s_rbase[r], n = s_rn[r];
        g_mat[base + s_rrank[r] * n + crank[rjx]] = d;
        if (!diag) g_mat[base + crank[rjx] * n + s_rrank[r]] = d;
    };

    float csum[8];
    #pragma unroll
    for (int x = 0; x < 8; x++) csum[x] = 0.f;

    #pragma unroll
    for (int mi = 0; mi < 2; mi++) {
        int r0  = wm * 32 + mi * 16 + qrow;
        int lr0 = s_rlab[r0];
        int lr1 = s_rlab[r0 + 8];
        float s0 = 0.f, s1 = 0.f;
        #pragma unroll
        for (int ni = 0; ni < 4; ni++) {
            int c0  = wn * 32 + ni * 8 + qcol;
            int lc0 = clab[ni * 2];
            int lc1 = clab[ni * 2 + 1];
            float f00 = (float)acc[mi][ni][0];
            float f01 = (float)acc[mi][ni][1];
            float f10 = (float)acc[mi][ni][2];
            float f11 = (float)acc[mi][ni][3];
            float e00 = (lr0 != lc0) ? __expf(f00 * EC) : 0.f;
            float e01 = (lr0 != lc1) ? __expf(f01 * EC) : 0.f;
            float e10 = (lr1 != lc0) ? __expf(f10 * EC) : 0.f;
            float e11 = (lr1 != lc1) ? __expf(f11 * EC) : 0.f;
            s0 += e00 + e01;
            s1 += e10 + e11;
            csum[ni * 2]     += e00 + e10;
            csum[ni * 2 + 1] += e01 + e11;
            if (lr0 == lc0 && (!diag || r0 != c0))
                emit(r0, ni * 2, f00 * DSCL);
            if (lr0 == lc1 && (!diag || r0 != c0 + 1))
                emit(r0, ni * 2 + 1, f01 * DSCL);
            if (lr1 == lc0 && (!diag || r0 + 8 != c0))
                emit(r0 + 8, ni * 2, f10 * DSCL);
            if (lr1 == lc1 && (!diag || r0 + 8 != c0 + 1))
                emit(r0 + 8, ni * 2 + 1, f11 * DSCL);
        }
        s0 += __shfl_xor_sync(0xffffffffu, s0, 1);
        s0 += __shfl_xor_sync(0xffffffffu, s0, 2);
        s1 += __shfl_xor_sync(0xffffffffu, s1, 1);
        s1 += __shfl_xor_sync(0xffffffffu, s1, 2);
        if ((lane & 3) == 0) {
            atomicAdd(&s_rows[r0],     s0);
            atomicAdd(&s_rows[r0 + 8], s1);
        }
    }

    if (!diag) {
        #pragma unroll
        for (int x = 0; x < 8; x++) {
            float cs = csum[x];
            #pragma unroll
            for (int o = 4; o <= 16; o <<= 1)
                cs += __shfl_xor_sync(0xffffffffu, cs, o);
            if (lane < 4)
                atomicAdd(&s_cols[wn * 32 + (x >> 1) * 8 + qcol + (x & 1)], cs);
        }
    }
    __syncthreads();
    if (t < BM) {
        atomicAdd(&g_sumneg[iBase + t], s_rows[t]);
        if (!diag) atomicAdd(&g_sumneg[jBase + t], s_cols[t]);
    }
}

// ============================================================================
// K3: per-row positive loss (warp per row) + fused finalize
// ============================================================================
__global__ __launch_bounds__(256) void k_rowloss(float* out) {
    __shared__ float s_p[8];
    __shared__ int   s_v[8];

    const int warp = threadIdx.x >> 5;
    const int lane = threadIdx.x & 31;
    const int i    = blockIdx.x * 8 + warp;

    const int l = g_lab[i];
    const int n = g_cls_cnt[l];
    float s = 0.f;
    if (n >= 2) {
        const int ri = g_rank[i];
        const float* row = g_mat + g_mat_off[l] + (size_t)ri * n;
        const float sn = g_sumneg[i];
        for (int rj = lane; rj < n; rj += 32)
            if (rj != ri)
                s += log1pf(sn * __expf(-row[rj] * INV_T));
        #pragma unroll
        for (int o = 16; o; o >>= 1)
            s += __shfl_xor_sync(0xffffffffu, s, o);
    }
    if (lane == 0) {
        s_p[warp] = (n >= 2) ? s / (float)(n - 1) : 0.f;
        s_v[warp] = (n >= 2) ? 1 : 0;
    }
    __syncthreads();
    if (threadIdx.x == 0) {
        float tp = 0.f; int tv = 0;
        #pragma unroll
        for (int w = 0; w < 8; w++) { tp += s_p[w]; tv += s_v[w]; }
        atomicAdd(&g_loss_sum, tp);
        atomicAdd(&g_valid, tv);
        __threadfence();
        int d = atomicAdd(&g_done, 1);
        if (d == gridDim.x - 1) {
            int v = g_valid;
            out[0] = (v > 0) ? g_loss_sum / (float)v : 0.f;
        }
    }
}

// ============================================================================
// launch
// ============================================================================
extern "C" void kernel_launch(void* const* d_in, const int* in_sizes, int n_in,
                              void* d_out, int out_size) {
    const float* z   = (const float*)d_in[0];
    const void*  lab = d_in[1];

    cudaFuncSetAttribute(k_gemm, cudaFuncAttributeMaxDynamicSharedMemorySize,
                         SMEM_GEMM);

    k_prep<<<1, 1024>>>(lab);
    k_cvt<<<(B_N * D_K / 4) / 256, 256>>>(z);
    k_gemm<<<NBLK * (NBLK + 1) / 2, 512, SMEM_GEMM>>>();
    k_rowloss<<<B_N / 8, 256>>>((float*)d_out);
}

// round 13
// speedup vs baseline: 1.5688x; 1.3410x over previous
#include <cuda_runtime.h>
#include <cuda_bf16.h>
#include <cstdint>

// ============================================================================
// Supervised contrastive loss, B=8192, D=256, NUM_CLASSES=100, T=0.07
//
// R13 = exact R9 gemm (the 94.5us winner: 256 thr, occ 2, 2-stage) plus:
//  - prep fused into cvt as one 1024-thread-block kernel (512 cvt blocks +
//    1 full-width prep block; R10's failed merge used 256-thr prep)
//  - k_rowloss: log1pf(x) -> __logf(1+x)  (abs err ~1e-6/pair, ~5x fewer
//    instructions in the dependent chain)
// ============================================================================

#define B_N   8192
#define D_K   256
#define NCLS  100
#define INV_T 14.285714285714285714f
#define DSCL  (1.f / 65536.f)
#define EC    (DSCL * INV_T)
#define MAT_CAP (1 << 21)

// ---- scratch ----
__device__ int8_t g_zq[B_N * D_K];
__device__ int    g_lab[B_N];
__device__ int    g_rank[B_N];
__device__ int    g_cls_cnt[NCLS];
__device__ int    g_mat_off[NCLS];
__device__ float  g_mat[MAT_CAP];
__device__ float  g_sumneg[B_N];
__device__ float  g_loss_sum;
__device__ int    g_valid;
__device__ int    g_done;

// ============================================================================
// K0: fused cvt (512 blocks x 1024 thr) + prep (block 512, 1024 thr)
// ============================================================================
#define CVT_BLOCKS (B_N * D_K / 4 / 1024)   // 512

__global__ __launch_bounds__(1024) void k_prep_cvt(const float* __restrict__ z,
                                                   const void* lab_raw) {
    if (blockIdx.x < CVT_BLOCKS) {
        int i = blockIdx.x * 1024 + threadIdx.x;
        float4 v = ((const float4*)z)[i];
        int a = max(-127, min(127, __float2int_rn(v.x * 256.f)));
        int b = max(-127, min(127, __float2int_rn(v.y * 256.f)));
        int c = max(-127, min(127, __float2int_rn(v.z * 256.f)));
        int d = max(-127, min(127, __float2int_rn(v.w * 256.f)));
        uint32_t p = (uint32_t)(a & 255) | ((uint32_t)(b & 255) << 8) |
                     ((uint32_t)(c & 255) << 16) | ((uint32_t)(d & 255) << 24);
        ((uint32_t*)g_zq)[i] = p;
        return;
    }

    // ---- prep: full 1024-thread block ----
    __shared__ int s_nonzero;
    __shared__ int s_cnt[NCLS];
    __shared__ int s_fill[NCLS];

    const int t = threadIdx.x;
    if (t == 0) s_nonzero = 0;
    for (int c = t; c < NCLS; c += 1024) { s_cnt[c] = 0; s_fill[c] = 0; }
    __syncthreads();

    const int* p32 = (const int*)lab_raw;
    // int64 LE labels in [0,100): every odd 32-bit word is 0.
    int local = 0;
    for (int i = t; i < B_N / 2; i += 1024)
        if (p32[2 * i + 1] != 0) local = 1;
    if (local) atomicOr(&s_nonzero, 1);
    __syncthreads();
    const bool is64 = (s_nonzero == 0);

    for (int i = t; i < B_N; i += 1024) {
        int l = is64 ? p32[2 * i] : p32[i];
        g_lab[i]    = l;
        g_sumneg[i] = 0.f;
        atomicAdd(&s_cnt[l], 1);
    }
    if (t == 0) { g_loss_sum = 0.f; g_valid = 0; g_done = 0; }
    __syncthreads();

    if (t == 0) {
        int acc = 0;
        for (int c = 0; c < NCLS; c++) {
            g_cls_cnt[c] = s_cnt[c];
            g_mat_off[c] = acc;
            acc += s_cnt[c] * s_cnt[c];
        }
    }
    __syncthreads();

    for (int i = t; i < B_N; i += 1024)
        g_rank[i] = atomicAdd(&s_fill[g_lab[i]], 1);
}

// ============================================================================
// K2: symmetric fused INT8 GEMM (exact R9 winner config)
// ============================================================================
#define BM   128
#define BN   128
#define BK   64
#define NBLK (B_N / BM)    // 64
#define LDTB 80

__device__ __forceinline__ void cp16(uint32_t dst, const void* src) {
    asm volatile("cp.async.cg.shared.global [%0], [%1], 16;\n" :: "r"(dst), "l"(src));
}

__device__ __forceinline__ void imma16832(int* c, const uint32_t* a, const uint32_t* b) {
    asm volatile(
        "mma.sync.aligned.m16n8k32.row.col.s32.s8.s8.s32 "
        "{%0,%1,%2,%3}, {%4,%5,%6,%7}, {%8,%9}, {%0,%1,%2,%3};"
        : "+r"(c[0]), "+r"(c[1]), "+r"(c[2]), "+r"(c[3])
        : "r"(a[0]), "r"(a[1]), "r"(a[2]), "r"(a[3]), "r"(b[0]), "r"(b[1]));
}

__global__ __launch_bounds__(256, 2) void k_gemm() {
    __shared__ __align__(16) int8_t sA[2][BM * LDTB];
    __shared__ __align__(16) int8_t sB[2][BN * LDTB];
    __shared__ int   s_rlab[BM];
    __shared__ int   s_clab[BN];
    __shared__ int   s_rrank[BM];
    __shared__ int   s_crank[BN];
    __shared__ int   s_rbase[BM];
    __shared__ int   s_rn[BM];
    __shared__ float s_rows[BM];
    __shared__ float s_cols[BN];

    const int t    = threadIdx.x;
    const int warp = t >> 5;
    const int lane = t & 31;
    const int wm   = warp >> 2;
    const int wn   = warp & 3;

    // triangular decode: bid -> (bi, bj), bj >= bi
    int bi = 0, rem = blockIdx.x;
    #pragma unroll 1
    while (rem >= NBLK - bi) { rem -= NBLK - bi; bi++; }
    const int  bj   = bi + rem;
    const bool diag = (bi == bj);
    const int iBase = bi * BM;
    const int jBase = bj * BN;

    if (t < BM) {
        int lr = g_lab[iBase + t];
        s_rlab[t]  = lr;
        s_clab[t]  = g_lab[jBase + t];
        s_rrank[t] = g_rank[iBase + t];
        s_crank[t] = g_rank[jBase + t];
        s_rbase[t] = g_mat_off[lr];
        s_rn[t]    = g_cls_cnt[lr];
        s_rows[t]  = 0.f;
        s_cols[t]  = 0.f;
    }

    const int8_t* gA = g_zq + (size_t)iBase * D_K;
    const int8_t* gB = g_zq + (size_t)jBase * D_K;

    uint32_t aS[2], bS[2];
    aS[0] = (uint32_t)__cvta_generic_to_shared(&sA[0][0]);
    aS[1] = (uint32_t)__cvta_generic_to_shared(&sA[1][0]);
    bS[0] = (uint32_t)__cvta_generic_to_shared(&sB[0][0]);
    bS[1] = (uint32_t)__cvta_generic_to_shared(&sB[1][0]);

    int acc[4][4][4];
    #pragma unroll
    for (int a = 0; a < 4; a++)
        #pragma unroll
        for (int b = 0; b < 4; b++)
            #pragma unroll
            for (int r = 0; r < 4; r++) acc[a][b][r] = 0;

    auto load_stage = [&](int st, int kt) {
        int k0 = kt * BK;
        #pragma unroll
        for (int rep = 0; rep < 2; rep++) {
            int idx = t + rep * 256;
            int row = idx >> 2;
            int ch  = idx & 3;
            uint32_t so = (uint32_t)(row * LDTB + ch * 16);
            size_t   go = (size_t)row * D_K + k0 + ch * 16;
            cp16(aS[st] + so, gA + go);
            cp16(bS[st] + so, gB + go);
        }
        asm volatile("cp.async.commit_group;\n" ::);
    };

    load_stage(0, 0);

    const int NKT = D_K / BK;   // 4
    for (int kt = 0; kt < NKT; kt++) {
        int cur = kt & 1;
        asm volatile("cp.async.wait_group 0;\n" ::);
        __syncthreads();
        if (kt + 1 < NKT) load_stage((kt + 1) & 1, kt + 1);

        #pragma unroll
        for (int ks = 0; ks < 2; ks++) {
            const int kb = ks * 32;
            uint32_t af[4][4], bf[4][2];
            #pragma unroll
            for (int mi = 0; mi < 4; mi++) {
                int r = wm * 64 + mi * 16 + (lane & 15);
                int c = kb + ((lane >> 4) << 4);
                uint32_t addr = aS[cur] + (uint32_t)(r * LDTB + c);
                asm volatile(
                    "ldmatrix.sync.aligned.m8n8.x4.shared.b16 {%0,%1,%2,%3}, [%4];"
                    : "=r"(af[mi][0]), "=r"(af[mi][1]), "=r"(af[mi][2]), "=r"(af[mi][3])
                    : "r"(addr));
            }
            #pragma unroll
            for (int p = 0; p < 2; p++) {
                int m  = lane >> 3;
                int nr = wn * 32 + (p * 2 + (m >> 1)) * 8 + (lane & 7);
                int c  = kb + ((m & 1) << 4);
                uint32_t addr = bS[cur] + (uint32_t)(nr * LDTB + c);
                asm volatile(
                    "ldmatrix.sync.aligned.m8n8.x4.shared.b16 {%0,%1,%2,%3}, [%4];"
                    : "=r"(bf[2 * p][0]), "=r"(bf[2 * p][1]),
                      "=r"(bf[2 * p + 1][0]), "=r"(bf[2 * p + 1][1])
                    : "r"(addr));
            }
            #pragma unroll
            for (int mi = 0; mi < 4; mi++)
                #pragma unroll
                for (int ni = 0; ni < 4; ni++)
                    imma16832(acc[mi][ni], af[mi], bf[ni]);
        }
        __syncthreads();
    }

    // ---- epilogue ----
    const int qrow = lane >> 2;
    const int qcol = (lane & 3) * 2;

    int clab[8], crank[8];
    #pragma unroll
    for (int x = 0; x < 8; x++) {
        int c = wn * 32 + (x >> 1) * 8 + qcol + (x & 1);
        clab[x]  = s_clab[c];
        crank[x] = s_crank[c];
    }

    auto emit = [&](int r, int rjx, float d) {
        int base = s_rbase[r], n = s_rn[r];
        g_mat[base + s_rrank[r] * n + crank[rjx]] = d;
        if (!diag) g_mat[base + crank[rjx] * n + s_rrank[r]] = d;
    };

    float csum[8];
    #pragma unroll
    for (int x = 0; x < 8; x++) csum[x] = 0.f;

    #pragma unroll
    for (int mi = 0; mi < 4; mi++) {
        int r0  = wm * 64 + mi * 16 + qrow;
        int lr0 = s_rlab[r0];
        int lr1 = s_rlab[r0 + 8];
        float s0 = 0.f, s1 = 0.f;
        #pragma unroll
        for (int ni = 0; ni < 4; ni++) {
            int c0  = wn * 32 + ni * 8 + qcol;
            int lc0 = clab[ni * 2];
            int lc1 = clab[ni * 2 + 1];
            float f00 = (float)acc[mi][ni][0];
            float f01 = (float)acc[mi][ni][1];
            float f10 = (float)acc[mi][ni][2];
            float f11 = (float)acc[mi][ni][3];
            float e00 = (lr0 != lc0) ? __expf(f00 * EC) : 0.f;
            float e01 = (lr0 != lc1) ? __expf(f01 * EC) : 0.f;
            float e10 = (lr1 != lc0) ? __expf(f10 * EC) : 0.f;
            float e11 = (lr1 != lc1) ? __expf(f11 * EC) : 0.f;
            s0 += e00 + e01;
            s1 += e10 + e11;
            csum[ni * 2]     += e00 + e10;
            csum[ni * 2 + 1] += e01 + e11;
            if (lr0 == lc0 && (!diag || r0 != c0))
                emit(r0, ni * 2, f00 * DSCL);
            if (lr0 == lc1 && (!diag || r0 != c0 + 1))
                emit(r0, ni * 2 + 1, f01 * DSCL);
            if (lr1 == lc0 && (!diag || r0 + 8 != c0))
                emit(r0 + 8, ni * 2, f10 * DSCL);
            if (lr1 == lc1 && (!diag || r0 + 8 != c0 + 1))
                emit(r0 + 8, ni * 2 + 1, f11 * DSCL);
        }
        s0 += __shfl_xor_sync(0xffffffffu, s0, 1);
        s0 += __shfl_xor_sync(0xffffffffu, s0, 2);
        s1 += __shfl_xor_sync(0xffffffffu, s1, 1);
        s1 += __shfl_xor_sync(0xffffffffu, s1, 2);
        if ((lane & 3) == 0) {
            atomicAdd(&s_rows[r0],     s0);
            atomicAdd(&s_rows[r0 + 8], s1);
        }
    }

    if (!diag) {
        #pragma unroll
        for (int x = 0; x < 8; x++) {
            float cs = csum[x];
            #pragma unroll
            for (int o = 4; o <= 16; o <<= 1)
                cs += __shfl_xor_sync(0xffffffffu, cs, o);
            if (lane < 4)
                atomicAdd(&s_cols[wn * 32 + (x >> 1) * 8 + qcol + (x & 1)], cs);
        }
    }
    __syncthreads();
    if (t < BM) {
        atomicAdd(&g_sumneg[iBase + t], s_rows[t]);
        if (!diag) atomicAdd(&g_sumneg[jBase + t], s_cols[t]);
    }
}

// ============================================================================
// K3: per-row positive loss (warp per row) + fused finalize
// ============================================================================
__global__ __launch_bounds__(256) void k_rowloss(float* out) {
    __shared__ float s_p[8];
    __shared__ int   s_v[8];

    const int warp = threadIdx.x >> 5;
    const int lane = threadIdx.x & 31;
    const int i    = blockIdx.x * 8 + warp;

    const int l = g_lab[i];
    const int n = g_cls_cnt[l];
    float s = 0.f;
    if (n >= 2) {
        const int ri = g_rank[i];
        const float* row = g_mat + g_mat_off[l] + (size_t)ri * n;
        const float sn = g_sumneg[i];
        for (int rj = lane; rj < n; rj += 32)
            if (rj != ri)
                s += __logf(1.f + sn * __expf(-row[rj] * INV_T));
        #pragma unroll
        for (int o = 16; o; o >>= 1)
            s += __shfl_xor_sync(0xffffffffu, s, o);
    }
    if (lane == 0) {
        s_p[warp] = (n >= 2) ? s / (float)(n - 1) : 0.f;
        s_v[warp] = (n >= 2) ? 1 : 0;
    }
    __syncthreads();
    if (threadIdx.x == 0) {
        float tp = 0.f; int tv = 0;
        #pragma unroll
        for (int w = 0; w < 8; w++) { tp += s_p[w]; tv += s_v[w]; }
        atomicAdd(&g_loss_sum, tp);
        atomicAdd(&g_valid, tv);
        __threadfence();
        int d = atomicAdd(&g_done, 1);
        if (d == gridDim.x - 1) {
            int v = g_valid;
            out[0] = (v > 0) ? g_loss_sum / (float)v : 0.f;
        }
    }
}

// ============================================================================
// launch
// ============================================================================
extern "C" void kernel_launch(void* const* d_in, const int* in_sizes, int n_in,
                              void* d_out, int out_size) {
    const float* z   = (const float*)d_in[0];
    const void*  lab = d_in[1];

    k_prep_cvt<<<CVT_BLOCKS + 1, 1024>>>(z, lab);
    k_gemm<<<NBLK * (NBLK + 1) / 2, 256>>>();
    k_rowloss<<<B_N / 8, 256>>>((float*)d_out);
}